// round 12
// baseline (speedup 1.0000x reference)
#include <cuda_runtime.h>
#include <cuda_fp16.h>
#include <cstdint>
#include <cstddef>

#define DEVINL __device__ __forceinline__

constexpr int HID = 4096, INTR = 16384, MTOK = 8192;
constexpr float LNEPS = 1e-5f;
constexpr int BM = 128, BN = 128, BK = 64, STAGES = 3, NTHR = 128;
constexpr int A_BYTES = BM * BK * 2;
constexpr int B_BYTES = BN * BK * 2;
constexpr int STAGE_BYTES = A_BYTES + B_BYTES;
constexpr int SMEM_SZ = STAGES * STAGE_BYTES;     // 98304

// ------------------------------------------------------------- scratch
__device__ float  g_res[(size_t)MTOK * HID];
__device__ __half g_ln [(size_t)MTOK * HID];
__device__ __half g_w1t[(size_t)INTR * HID];
__device__ __half g_w2t[(size_t)HID * INTR];
__device__ __half g_int[(size_t)MTOK * INTR];

// ------------------------------------------------------------- PTX helpers
DEVINL uint32_t smem_u32(const void* p) {
    uint32_t a;
    asm("{ .reg .u64 t; cvta.to.shared.u64 t, %1; cvt.u32.u64 %0, t; }" : "=r"(a) : "l"(p));
    return a;
}
DEVINL void cp16(uint32_t dst, const void* src) {
    asm volatile("cp.async.cg.shared.global [%0], [%1], 16;" :: "r"(dst), "l"(src));
}
DEVINL void ldsm_x4(uint32_t& r0, uint32_t& r1, uint32_t& r2, uint32_t& r3, uint32_t addr) {
    asm volatile("ldmatrix.sync.aligned.m8n8.x4.shared.b16 {%0,%1,%2,%3}, [%4];"
                 : "=r"(r0), "=r"(r1), "=r"(r2), "=r"(r3) : "r"(addr));
}
DEVINL void mma16816(float* c, const uint32_t* a, const uint32_t* b) {
    asm volatile(
        "mma.sync.aligned.m16n8k16.row.col.f32.f16.f16.f32 "
        "{%0,%1,%2,%3}, {%4,%5,%6,%7}, {%8,%9}, {%0,%1,%2,%3};"
        : "+f"(c[0]), "+f"(c[1]), "+f"(c[2]), "+f"(c[3])
        : "r"(a[0]), "r"(a[1]), "r"(a[2]), "r"(a[3]), "r"(b[0]), "r"(b[1]));
}
DEVINL float gelu(float x) {
    float u = 0.7978845608f * (x + 0.044715f * x * x * x);
    float t;
    asm("tanh.approx.f32 %0, %1;" : "=f"(t) : "f"(u));
    return 0.5f * x * (1.f + t);
}

// ------------------------------------------------------------- K0: residual add + LN
__global__ void __launch_bounds__(256) ln_kernel(
    const float* __restrict__ in, const float* __restrict__ resid,
    const float* __restrict__ bias, const float* __restrict__ gamma,
    const float* __restrict__ beta)
{
    const size_t base = (size_t)blockIdx.x * HID;
    const int tid = threadIdx.x, wid = tid >> 5, lane = tid & 31;
    float4 v[4];
    float s = 0.f, s2 = 0.f;
#pragma unroll
    for (int i = 0; i < 4; i++) {
        int idx = (tid + i * 256) * 4;
        float4 a = *(const float4*)(in + base + idx);
        float4 b = *(const float4*)(resid + base + idx);
        float4 c = *(const float4*)(bias + idx);
        a.x += b.x + c.x; a.y += b.y + c.y; a.z += b.z + c.z; a.w += b.w + c.w;
        v[i] = a;
        s  += a.x + a.y + a.z + a.w;
        s2 += a.x*a.x + a.y*a.y + a.z*a.z + a.w*a.w;
    }
#pragma unroll
    for (int o = 16; o; o >>= 1) {
        s  += __shfl_xor_sync(~0u, s, o);
        s2 += __shfl_xor_sync(~0u, s2, o);
    }
    __shared__ float rs[8], rq[8];
    if (lane == 0) { rs[wid] = s; rq[wid] = s2; }
    __syncthreads();
    float S = 0.f, S2 = 0.f;
#pragma unroll
    for (int w = 0; w < 8; w++) { S += rs[w]; S2 += rq[w]; }
    const float mu = S * (1.f / HID);
    const float var = S2 * (1.f / HID) - mu * mu;
    const float rstd = rsqrtf(var + LNEPS);
#pragma unroll
    for (int i = 0; i < 4; i++) {
        int idx = (tid + i * 256) * 4;
        *(float4*)(g_res + base + idx) = v[i];
        float4 g = *(const float4*)(gamma + idx);
        float4 bb = *(const float4*)(beta + idx);
        float l0 = (v[i].x - mu) * rstd * g.x + bb.x;
        float l1 = (v[i].y - mu) * rstd * g.y + bb.y;
        float l2 = (v[i].z - mu) * rstd * g.z + bb.z;
        float l3 = (v[i].w - mu) * rstd * g.w + bb.w;
        __half2 h0 = __floats2half2_rn(l0, l1);
        __half2 h1 = __floats2half2_rn(l2, l3);
        uint2 pk = make_uint2(*(uint32_t*)&h0, *(uint32_t*)&h1);
        *(uint2*)(g_ln + base + idx) = pk;
    }
}

// ------------------------------------------------------------- transpose fp32 [R,C] -> fp16 [C,R]
__global__ void __launch_bounds__(256) tr_kernel(
    const float* __restrict__ in, __half* __restrict__ out, int R, int C)
{
    __shared__ __half tile[64 * 64];
    char* tb = (char*)tile;
    const int c0 = blockIdx.x * 64, r0 = blockIdx.y * 64;
    const int tid = threadIdx.x;
#pragma unroll
    for (int i = 0; i < 4; i++) {
        int t = tid + i * 256;
        int row = t >> 4, col4 = t & 15;
        float4 v = *(const float4*)(in + (size_t)(r0 + row) * C + c0 + col4 * 4);
        const int cB = col4 * 4;
#pragma unroll
        for (int k = 0; k < 4; k++) {
            int c = cB + k;
            float f = (k == 0) ? v.x : (k == 1) ? v.y : (k == 2) ? v.z : v.w;
            uint32_t off = (uint32_t)(c * 128) + (uint32_t)((row * 2) ^ ((c & 7) << 4));
            *(__half*)(tb + off) = __float2half(f);
        }
    }
    __syncthreads();
#pragma unroll
    for (int it = 0; it < 2; it++) {
        int cc = (tid >> 3) + it * 32;
        int seg = tid & 7;
        uint32_t off = (uint32_t)(cc * 128) + (uint32_t)((seg * 16) ^ ((cc & 7) << 4));
        uint4 v = *(const uint4*)(tb + off);
        *(uint4*)(out + (size_t)(c0 + cc) * R + r0 + seg * 8) = v;
    }
}

// ------------------------------------------------------------- GEMM 128x128x64, mma.sync f16
// 128 thr (2 CTA/SM), warp 64x64, 3-stage cp.async.
// Rotated pipeline: wait+barrier at loop tail, ks0 frags of next tile prefetched
// post-barrier so each iteration opens with MMAs, not LDSM latency.
template <int EPI>
__global__ void __launch_bounds__(NTHR, 2) gemm_kernel(
    const __half* __restrict__ A, const __half* __restrict__ B, int K,
    const float* __restrict__ bias, const float* __restrict__ res,
    __half* __restrict__ outh, float* __restrict__ outf, int ldo)
{
    extern __shared__ char smem[];
    const uint32_t sbase = smem_u32(smem);
    const int tid = threadIdx.x, wid = tid >> 5, lane = tid & 31;
    const int wm = wid & 1, wn = wid >> 1;
    const int m0 = blockIdx.x * BM, n0 = blockIdx.y * BN;
    const int KT = K / BK;

    auto load_stage = [&](int j) {
        const int s = j % STAGES;
        const uint32_t sa = sbase + s * STAGE_BYTES;
        const uint32_t sb = sa + A_BYTES;
        const __half* ga = A + (size_t)m0 * K + (size_t)j * BK;
        const __half* gb = B + (size_t)n0 * K + (size_t)j * BK;
#pragma unroll
        for (int i = 0; i < 8; i++) {
            int c = tid + i * NTHR;
            int row = c >> 3, kc = c & 7;
            uint32_t sw = row * 128 + ((kc ^ (row & 7)) << 4);
            cp16(sa + sw, ga + (size_t)row * K + kc * 8);
        }
#pragma unroll
        for (int i = 0; i < 8; i++) {
            int c = tid + i * NTHR;
            int row = c >> 3, kc = c & 7;
            uint32_t sw = row * 128 + ((kc ^ (row & 7)) << 4);
            cp16(sb + sw, gb + (size_t)row * K + kc * 8);
        }
    };

    float acc[4][8][4];
#pragma unroll
    for (int i = 0; i < 4; i++)
#pragma unroll
        for (int j = 0; j < 8; j++)
#pragma unroll
            for (int k = 0; k < 4; k++) acc[i][j][k] = 0.f;

    const int tlane = lane >> 3, rlane = lane & 7;

    auto load_b = [&](uint32_t sb, int ks, uint32_t (*bf)[4]) {
#pragma unroll
        for (int nt2 = 0; nt2 < 4; nt2++) {
            int nrow = wn * 64 + (nt2 * 2 + (tlane >> 1)) * 8 + rlane;
            int kc = ks * 2 + (tlane & 1);
            uint32_t addr = sb + nrow * 128 + ((kc ^ (nrow & 7)) << 4);
            ldsm_x4(bf[nt2][0], bf[nt2][1], bf[nt2][2], bf[nt2][3], addr);
        }
    };
    auto load_a = [&](uint32_t sa, int ks, uint32_t (*af)[4]) {
#pragma unroll
        for (int mt = 0; mt < 4; mt++) {
            int row = wm * 64 + mt * 16 + ((tlane & 1) << 3) + rlane;
            int kc = ks * 2 + (tlane >> 1);
            uint32_t addr = sa + row * 128 + ((kc ^ (row & 7)) << 4);
            ldsm_x4(af[mt][0], af[mt][1], af[mt][2], af[mt][3], addr);
        }
    };

    // prologue: tiles 0,1 in flight; make tile 0 visible; preload its ks0 frags
    load_stage(0);
    asm volatile("cp.async.commit_group;");
    load_stage(1);
    asm volatile("cp.async.commit_group;");
    asm volatile("cp.async.wait_group 1;");
    __syncthreads();

    uint32_t af[2][4][4], bf[2][4][4];
    load_a(sbase, 0, af[0]);
    load_b(sbase + A_BYTES, 0, bf[0]);

    for (int j = 0; j < KT; j++) {
        const uint32_t sa = sbase + (j % STAGES) * STAGE_BYTES;
        const uint32_t sb = sa + A_BYTES;
#pragma unroll
        for (int ks = 0; ks < 4; ks++) {
            if (ks < 3) {
                load_a(sa, ks + 1, af[(ks + 1) & 1]);
                load_b(sb, ks + 1, bf[(ks + 1) & 1]);
            }
            if (ks == 0) {
                const int jn = j + 2;
                if (jn < KT) load_stage(jn);
                asm volatile("cp.async.commit_group;");  // empty group ok: keeps accounting uniform
            }
#pragma unroll
            for (int mt = 0; mt < 4; mt++)
#pragma unroll
                for (int nt = 0; nt < 8; nt++)
                    mma16816(acc[mt][nt], af[ks & 1][mt], &bf[ks & 1][nt >> 1][(nt & 1) * 2]);
        }
        if (j + 1 < KT) {
            asm volatile("cp.async.wait_group 1;");  // pending <= {t_{j+1}, t_{j+2}} -> t_{j+1} arrived
            __syncthreads();                          // cross-thread visibility + stage-reuse protection
            const uint32_t na = sbase + ((j + 1) % STAGES) * STAGE_BYTES;
            load_a(na, 0, af[0]);
            load_b(na + A_BYTES, 0, bf[0]);
        }
    }

    // epilogue
    const int rbase = m0 + wm * 64 + (lane >> 2);
    const int cbase = n0 + wn * 64 + (lane & 3) * 2;
#pragma unroll
    for (int mt = 0; mt < 4; mt++) {
#pragma unroll
        for (int nt = 0; nt < 8; nt++) {
            int col = cbase + nt * 8;
            float b0 = bias[col], b1 = bias[col + 1];
#pragma unroll
            for (int h = 0; h < 2; h++) {
                int row = rbase + mt * 16 + h * 8;
                float x0 = acc[mt][nt][h * 2 + 0] + b0;
                float x1 = acc[mt][nt][h * 2 + 1] + b1;
                if (EPI == 0) {
                    __half2 hh = __floats2half2_rn(gelu(x0), gelu(x1));
                    *(uint32_t*)(outh + (size_t)row * ldo + col) = *(uint32_t*)&hh;
                } else {
                    const float2 rv = *(const float2*)(res + (size_t)row * ldo + col);
                    float2 o = make_float2(x0 + rv.x, x1 + rv.y);
                    *(float2*)(outf + (size_t)row * ldo + col) = o;
                }
            }
        }
    }
}

// ------------------------------------------------------------- launch
extern "C" void kernel_launch(void* const* d_in, const int* in_sizes, int n_in,
                              void* d_out, int out_size)
{
    const float* input    = (const float*)d_in[0];
    const float* residual = (const float*)d_in[1];
    const float* bias     = (const float*)d_in[3];
    const float* attn_nw  = (const float*)d_in[4];
    const float* attn_nb  = (const float*)d_in[5];
    const float* inter_w  = (const float*)d_in[6];
    const float* inter_b  = (const float*)d_in[7];
    const float* output_w = (const float*)d_in[8];
    const float* output_b = (const float*)d_in[9];
    float* out = (float*)d_out;

    void *p_res, *p_ln, *p_w1t, *p_w2t, *p_int;
    cudaGetSymbolAddress(&p_res, g_res);
    cudaGetSymbolAddress(&p_ln,  g_ln);
    cudaGetSymbolAddress(&p_w1t, g_w1t);
    cudaGetSymbolAddress(&p_w2t, g_w2t);
    cudaGetSymbolAddress(&p_int, g_int);

    cudaFuncSetAttribute(gemm_kernel<0>, cudaFuncAttributeMaxDynamicSharedMemorySize, SMEM_SZ);
    cudaFuncSetAttribute(gemm_kernel<1>, cudaFuncAttributeMaxDynamicSharedMemorySize, SMEM_SZ);

    ln_kernel<<<MTOK, 256>>>(input, residual, bias, attn_nw, attn_nb);
    tr_kernel<<<dim3(INTR / 64, HID / 64), 256>>>(inter_w, (__half*)p_w1t, HID, INTR);
    tr_kernel<<<dim3(HID / 64, INTR / 64), 256>>>(output_w, (__half*)p_w2t, INTR, HID);

    gemm_kernel<0><<<dim3(MTOK / BM, INTR / BN), NTHR, SMEM_SZ>>>(
        (const __half*)p_ln, (const __half*)p_w1t, HID,
        inter_b, nullptr, (__half*)p_int, nullptr, INTR);

    gemm_kernel<1><<<dim3(MTOK / BM, HID / BN), NTHR, SMEM_SZ>>>(
        (const __half*)p_int, (const __half*)p_w2t, INTR,
        output_b, (const float*)p_res, nullptr, out, HID);
}

// round 13
// speedup vs baseline: 1.0655x; 1.0655x over previous
#include <cuda_runtime.h>
#include <cuda_fp16.h>
#include <cstdint>
#include <cstddef>

#define DEVINL __device__ __forceinline__

constexpr int HID = 4096, INTR = 16384, MTOK = 8192;
constexpr float LNEPS = 1e-5f;
constexpr int BM = 128, BN = 128, BK = 64, STAGES = 3, NTHR = 128;
constexpr int A_BYTES = BM * BK * 2;
constexpr int B_BYTES = BN * BK * 2;
constexpr int STAGE_BYTES = A_BYTES + B_BYTES;
constexpr int SMEM_SZ = STAGES * STAGE_BYTES;     // 98304

// ------------------------------------------------------------- scratch
__device__ float  g_res[(size_t)MTOK * HID];
__device__ __half g_ln [(size_t)MTOK * HID];
__device__ __half g_w1t[(size_t)INTR * HID];
__device__ __half g_w2t[(size_t)HID * INTR];
__device__ __half g_int[(size_t)MTOK * INTR];

// ------------------------------------------------------------- PTX helpers
DEVINL uint32_t smem_u32(const void* p) {
    uint32_t a;
    asm("{ .reg .u64 t; cvta.to.shared.u64 t, %1; cvt.u32.u64 %0, t; }" : "=r"(a) : "l"(p));
    return a;
}
DEVINL void cp16(uint32_t dst, const void* src) {
    asm volatile("cp.async.cg.shared.global [%0], [%1], 16;" :: "r"(dst), "l"(src));
}
DEVINL void ldsm_x4(uint32_t& r0, uint32_t& r1, uint32_t& r2, uint32_t& r3, uint32_t addr) {
    asm volatile("ldmatrix.sync.aligned.m8n8.x4.shared.b16 {%0,%1,%2,%3}, [%4];"
                 : "=r"(r0), "=r"(r1), "=r"(r2), "=r"(r3) : "r"(addr));
}
DEVINL void mma16816(float* c, const uint32_t* a, const uint32_t* b) {
    asm volatile(
        "mma.sync.aligned.m16n8k16.row.col.f32.f16.f16.f32 "
        "{%0,%1,%2,%3}, {%4,%5,%6,%7}, {%8,%9}, {%0,%1,%2,%3};"
        : "+f"(c[0]), "+f"(c[1]), "+f"(c[2]), "+f"(c[3])
        : "r"(a[0]), "r"(a[1]), "r"(a[2]), "r"(a[3]), "r"(b[0]), "r"(b[1]));
}
DEVINL float gelu(float x) {
    float u = 0.7978845608f * (x + 0.044715f * x * x * x);
    float t;
    asm("tanh.approx.f32 %0, %1;" : "=f"(t) : "f"(u));
    return 0.5f * x * (1.f + t);
}

// ------------------------------------------------------------- K0: residual add + LN
__global__ void __launch_bounds__(256) ln_kernel(
    const float* __restrict__ in, const float* __restrict__ resid,
    const float* __restrict__ bias, const float* __restrict__ gamma,
    const float* __restrict__ beta)
{
    const size_t base = (size_t)blockIdx.x * HID;
    const int tid = threadIdx.x, wid = tid >> 5, lane = tid & 31;
    float4 v[4];
    float s = 0.f, s2 = 0.f;
#pragma unroll
    for (int i = 0; i < 4; i++) {
        int idx = (tid + i * 256) * 4;
        float4 a = *(const float4*)(in + base + idx);
        float4 b = *(const float4*)(resid + base + idx);
        float4 c = *(const float4*)(bias + idx);
        a.x += b.x + c.x; a.y += b.y + c.y; a.z += b.z + c.z; a.w += b.w + c.w;
        v[i] = a;
        s  += a.x + a.y + a.z + a.w;
        s2 += a.x*a.x + a.y*a.y + a.z*a.z + a.w*a.w;
    }
#pragma unroll
    for (int o = 16; o; o >>= 1) {
        s  += __shfl_xor_sync(~0u, s, o);
        s2 += __shfl_xor_sync(~0u, s2, o);
    }
    __shared__ float rs[8], rq[8];
    if (lane == 0) { rs[wid] = s; rq[wid] = s2; }
    __syncthreads();
    float S = 0.f, S2 = 0.f;
#pragma unroll
    for (int w = 0; w < 8; w++) { S += rs[w]; S2 += rq[w]; }
    const float mu = S * (1.f / HID);
    const float var = S2 * (1.f / HID) - mu * mu;
    const float rstd = rsqrtf(var + LNEPS);
#pragma unroll
    for (int i = 0; i < 4; i++) {
        int idx = (tid + i * 256) * 4;
        *(float4*)(g_res + base + idx) = v[i];
        float4 g = *(const float4*)(gamma + idx);
        float4 bb = *(const float4*)(beta + idx);
        float l0 = (v[i].x - mu) * rstd * g.x + bb.x;
        float l1 = (v[i].y - mu) * rstd * g.y + bb.y;
        float l2 = (v[i].z - mu) * rstd * g.z + bb.z;
        float l3 = (v[i].w - mu) * rstd * g.w + bb.w;
        __half2 h0 = __floats2half2_rn(l0, l1);
        __half2 h1 = __floats2half2_rn(l2, l3);
        uint2 pk = make_uint2(*(uint32_t*)&h0, *(uint32_t*)&h1);
        *(uint2*)(g_ln + base + idx) = pk;
    }
}

// ------------------------------------------------------------- transpose fp32 [R,C] -> fp16 [C,R]
__global__ void __launch_bounds__(256) tr_kernel(
    const float* __restrict__ in, __half* __restrict__ out, int R, int C)
{
    __shared__ __half tile[64 * 64];
    char* tb = (char*)tile;
    const int c0 = blockIdx.x * 64, r0 = blockIdx.y * 64;
    const int tid = threadIdx.x;
#pragma unroll
    for (int i = 0; i < 4; i++) {
        int t = tid + i * 256;
        int row = t >> 4, col4 = t & 15;
        float4 v = *(const float4*)(in + (size_t)(r0 + row) * C + c0 + col4 * 4);
        const int cB = col4 * 4;
#pragma unroll
        for (int k = 0; k < 4; k++) {
            int c = cB + k;
            float f = (k == 0) ? v.x : (k == 1) ? v.y : (k == 2) ? v.z : v.w;
            uint32_t off = (uint32_t)(c * 128) + (uint32_t)((row * 2) ^ ((c & 7) << 4));
            *(__half*)(tb + off) = __float2half(f);
        }
    }
    __syncthreads();
#pragma unroll
    for (int it = 0; it < 2; it++) {
        int cc = (tid >> 3) + it * 32;
        int seg = tid & 7;
        uint32_t off = (uint32_t)(cc * 128) + (uint32_t)((seg * 16) ^ ((cc & 7) << 4));
        uint4 v = *(const uint4*)(tb + off);
        *(uint4*)(out + (size_t)(c0 + cc) * R + r0 + seg * 8) = v;
    }
}

// ------------------------------------------------------------- GEMM 128x128x64, mma.sync f16
// 128 thr (2 CTA/SM), warp 64x64, 3-stage cp.async. R6-proven loop; only change:
// next-tile cp.async split A-half at ks=0, B-half at ks=1 (commit after B-half)
// to avoid a 16-op LSU burst colliding with ks=1 LDSMs.
template <int EPI>
__global__ void __launch_bounds__(NTHR, 2) gemm_kernel(
    const __half* __restrict__ A, const __half* __restrict__ B, int K,
    const float* __restrict__ bias, const float* __restrict__ res,
    __half* __restrict__ outh, float* __restrict__ outf, int ldo)
{
    extern __shared__ char smem[];
    const uint32_t sbase = smem_u32(smem);
    const int tid = threadIdx.x, wid = tid >> 5, lane = tid & 31;
    const int wm = wid & 1, wn = wid >> 1;
    const int m0 = blockIdx.x * BM, n0 = blockIdx.y * BN;
    const int KT = K / BK;

    auto load_stage_a = [&](int j) {
        const int s = j % STAGES;
        const uint32_t sa = sbase + s * STAGE_BYTES;
        const __half* ga = A + (size_t)m0 * K + (size_t)j * BK;
#pragma unroll
        for (int i = 0; i < 8; i++) {
            int c = tid + i * NTHR;
            int row = c >> 3, kc = c & 7;
            uint32_t sw = row * 128 + ((kc ^ (row & 7)) << 4);
            cp16(sa + sw, ga + (size_t)row * K + kc * 8);
        }
    };
    auto load_stage_b = [&](int j) {
        const int s = j % STAGES;
        const uint32_t sb = sbase + s * STAGE_BYTES + A_BYTES;
        const __half* gb = B + (size_t)n0 * K + (size_t)j * BK;
#pragma unroll
        for (int i = 0; i < 8; i++) {
            int c = tid + i * NTHR;
            int row = c >> 3, kc = c & 7;
            uint32_t sw = row * 128 + ((kc ^ (row & 7)) << 4);
            cp16(sb + sw, gb + (size_t)row * K + kc * 8);
        }
    };

    float acc[4][8][4];
#pragma unroll
    for (int i = 0; i < 4; i++)
#pragma unroll
        for (int j = 0; j < 8; j++)
#pragma unroll
            for (int k = 0; k < 4; k++) acc[i][j][k] = 0.f;

    for (int j = 0; j < STAGES - 1; j++) {
        load_stage_a(j);
        load_stage_b(j);
        asm volatile("cp.async.commit_group;");
    }

    const int tlane = lane >> 3, rlane = lane & 7;

    auto load_b = [&](uint32_t sb, int ks, uint32_t (*bf)[4]) {
#pragma unroll
        for (int nt2 = 0; nt2 < 4; nt2++) {
            int nrow = wn * 64 + (nt2 * 2 + (tlane >> 1)) * 8 + rlane;
            int kc = ks * 2 + (tlane & 1);
            uint32_t addr = sb + nrow * 128 + ((kc ^ (nrow & 7)) << 4);
            ldsm_x4(bf[nt2][0], bf[nt2][1], bf[nt2][2], bf[nt2][3], addr);
        }
    };
    auto load_a = [&](uint32_t sa, int ks, uint32_t (*af)[4]) {
#pragma unroll
        for (int mt = 0; mt < 4; mt++) {
            int row = wm * 64 + mt * 16 + ((tlane & 1) << 3) + rlane;
            int kc = ks * 2 + (tlane >> 1);
            uint32_t addr = sa + row * 128 + ((kc ^ (row & 7)) << 4);
            ldsm_x4(af[mt][0], af[mt][1], af[mt][2], af[mt][3], addr);
        }
    };

    for (int j = 0; j < KT; j++) {
        asm volatile("cp.async.wait_group %0;" :: "n"(STAGES - 2));
        __syncthreads();

        const int s = j % STAGES;
        const uint32_t sa = sbase + s * STAGE_BYTES;
        const uint32_t sb = sa + A_BYTES;
        const int jn = j + STAGES - 1;
        const bool pf = jn < KT;

        uint32_t af[2][4][4], bf[2][4][4];
        load_a(sa, 0, af[0]);
        load_b(sb, 0, bf[0]);
#pragma unroll
        for (int ks = 0; ks < 4; ks++) {
            if (ks < 3) {
                load_a(sa, ks + 1, af[(ks + 1) & 1]);
                load_b(sb, ks + 1, bf[(ks + 1) & 1]);
            }
#pragma unroll
            for (int mt = 0; mt < 4; mt++)
#pragma unroll
                for (int nt = 0; nt < 8; nt++)
                    mma16816(acc[mt][nt], af[ks & 1][mt], &bf[ks & 1][nt >> 1][(nt & 1) * 2]);
            if (ks == 0) {
                if (pf) load_stage_a(jn);
            } else if (ks == 1) {
                if (pf) load_stage_b(jn);
                asm volatile("cp.async.commit_group;");
            }
        }
    }

    // epilogue
    const int rbase = m0 + wm * 64 + (lane >> 2);
    const int cbase = n0 + wn * 64 + (lane & 3) * 2;
#pragma unroll
    for (int mt = 0; mt < 4; mt++) {
#pragma unroll
        for (int nt = 0; nt < 8; nt++) {
            int col = cbase + nt * 8;
            float b0 = bias[col], b1 = bias[col + 1];
#pragma unroll
            for (int h = 0; h < 2; h++) {
                int row = rbase + mt * 16 + h * 8;
                float x0 = acc[mt][nt][h * 2 + 0] + b0;
                float x1 = acc[mt][nt][h * 2 + 1] + b1;
                if (EPI == 0) {
                    __half2 hh = __floats2half2_rn(gelu(x0), gelu(x1));
                    *(uint32_t*)(outh + (size_t)row * ldo + col) = *(uint32_t*)&hh;
                } else {
                    const float2 rv = *(const float2*)(res + (size_t)row * ldo + col);
                    float2 o = make_float2(x0 + rv.x, x1 + rv.y);
                    *(float2*)(outf + (size_t)row * ldo + col) = o;
                }
            }
        }
    }
}

// ------------------------------------------------------------- launch
extern "C" void kernel_launch(void* const* d_in, const int* in_sizes, int n_in,
                              void* d_out, int out_size)
{
    const float* input    = (const float*)d_in[0];
    const float* residual = (const float*)d_in[1];
    const float* bias     = (const float*)d_in[3];
    const float* attn_nw  = (const float*)d_in[4];
    const float* attn_nb  = (const float*)d_in[5];
    const float* inter_w  = (const float*)d_in[6];
    const float* inter_b  = (const float*)d_in[7];
    const float* output_w = (const float*)d_in[8];
    const float* output_b = (const float*)d_in[9];
    float* out = (float*)d_out;

    void *p_res, *p_ln, *p_w1t, *p_w2t, *p_int;
    cudaGetSymbolAddress(&p_res, g_res);
    cudaGetSymbolAddress(&p_ln,  g_ln);
    cudaGetSymbolAddress(&p_w1t, g_w1t);
    cudaGetSymbolAddress(&p_w2t, g_w2t);
    cudaGetSymbolAddress(&p_int, g_int);

    cudaFuncSetAttribute(gemm_kernel<0>, cudaFuncAttributeMaxDynamicSharedMemorySize, SMEM_SZ);
    cudaFuncSetAttribute(gemm_kernel<1>, cudaFuncAttributeMaxDynamicSharedMemorySize, SMEM_SZ);

    ln_kernel<<<MTOK, 256>>>(input, residual, bias, attn_nw, attn_nb);
    tr_kernel<<<dim3(INTR / 64, HID / 64), 256>>>(inter_w, (__half*)p_w1t, HID, INTR);
    tr_kernel<<<dim3(HID / 64, INTR / 64), 256>>>(output_w, (__half*)p_w2t, INTR, HID);

    gemm_kernel<0><<<dim3(MTOK / BM, INTR / BN), NTHR, SMEM_SZ>>>(
        (const __half*)p_ln, (const __half*)p_w1t, HID,
        inter_b, nullptr, (__half*)p_int, nullptr, INTR);

    gemm_kernel<1><<<dim3(MTOK / BM, HID / BN), NTHR, SMEM_SZ>>>(
        (const __half*)p_int, (const __half*)p_w2t, INTR,
        output_b, (const float*)p_res, nullptr, out, HID);
}